// round 14
// baseline (speedup 1.0000x reference)
#include <cuda_runtime.h>
#include <cuda_fp16.h>
#include <float.h>

#define NIMG 32
#define H    512
#define W    512
#define HW   (H * W)
#define CHW  (3 * HW)

#define NEG2 0xFC00FC00u      // half2(-inf, -inf)

#define VBLK  (NIMG * 16 * 2)        // 1024 blocks: (img, 32-row strip, col half)

__device__ __half g_hmax[NIMG * HW]; // fp16 intermediate (16.75 MB, L2-resident)
__device__ float  g_partial[VBLK];
__device__ int    g_count;           // zero-init; reset by last block

__device__ __forceinline__ unsigned hmax2u(unsigned a, unsigned b) {
    __half2 ha = *reinterpret_cast<__half2*>(&a);
    __half2 hb = *reinterpret_cast<__half2*>(&b);
    __half2 hm = __hmax2(ha, hb);
    return *reinterpret_cast<unsigned*>(&hm);
}
__device__ __forceinline__ unsigned sh1(unsigned a, unsigned b) {
    return __byte_perm(a, b, 0x5432);   // (a.hi, b.lo)
}

// ---------------------------------------------------------------------------
// Kernel 1: warp-autonomous hpass. One warp per image row; 8 warps/block;
// per-warp smem buffers; no __syncthreads (only __syncwarp).
// Pipeline per row (identical math to the verified R4 stage-1):
//   c = 1 - min3(channels) -> packed half2; width-5 sliding max; 7-tap combine.
// ---------------------------------------------------------------------------
__global__ __launch_bounds__(256) void hpass_kernel(const float* __restrict__ img) {
    __shared__ unsigned s2[8][280];
    __shared__ unsigned t2[8][280];

    const int wid  = threadIdx.x >> 5;
    const int lane = threadIdx.x & 31;
    const int row  = (blockIdx.x << 3) + wid;      // 0 .. NIMG*H-1
    const int n    = row >> 9;
    const int h    = row & (H - 1);
    const float* prow = img + (size_t)n * CHW + (size_t)h * W;

    unsigned* s2w = s2[wid];
    unsigned* t2w = t2[wid];

    if (lane < 10) { s2w[lane] = NEG2; s2w[266 + lane] = NEG2; }

    #pragma unroll
    for (int i = 0; i < 4; i++) {
        const int q = lane + (i << 5);             // px 4q..4q+3
        const float4 a = ((const float4*)prow)[q];
        const float4 b = ((const float4*)(prow + HW))[q];
        const float4 c = ((const float4*)(prow + 2 * HW))[q];
        float c0 = 1.0f - fminf(a.x, fminf(b.x, c.x));
        float c1 = 1.0f - fminf(a.y, fminf(b.y, c.y));
        float c2 = 1.0f - fminf(a.z, fminf(b.z, c.z));
        float c3 = 1.0f - fminf(a.w, fminf(b.w, c.w));
        __half2 h01 = __floats2half2_rn(c0, c1);
        __half2 h23 = __floats2half2_rn(c2, c3);
        s2w[2 * q + 10] = *reinterpret_cast<unsigned*>(&h01);
        s2w[2 * q + 11] = *reinterpret_cast<unsigned*>(&h23);
    }
    __syncwarp();

    // width-5 pass: t2[i] covers px (2i-20 .. 2i-16)/(2i-19 .. 2i-15)
    #pragma unroll
    for (int j = 0; j < 9; j++) {
        const int i = lane + (j << 5);
        if (i < 273) {
            const unsigned A = s2w[i], B = s2w[i + 1], C = s2w[i + 2];
            t2w[i] = hmax2u(hmax2u(hmax2u(A, sh1(A, B)),
                                   hmax2u(B, sh1(B, C))), C);
        }
    }
    __syncwarp();

    // 7-tap combine: outputs (2q, 2q+1)
    unsigned* orow = (unsigned*)(g_hmax + (size_t)row * W);
    #pragma unroll
    for (int j = 0; j < 8; j++) {
        const int q = lane + (j << 5);
        unsigned v;
        v = sh1(t2w[q + 1], t2w[q + 2]);
        v = hmax2u(v, t2w[q + 4]);
        v = hmax2u(v, sh1(t2w[q + 6], t2w[q + 7]));
        v = hmax2u(v, t2w[q + 9]);
        v = hmax2u(v, sh1(t2w[q + 11], t2w[q + 12]));
        v = hmax2u(v, t2w[q + 14]);
        v = hmax2u(v, sh1(t2w[q + 16], t2w[q + 17]));
        orow[q] = v;
    }
}

// ---------------------------------------------------------------------------
// Per-thread vertical 35-max column scan over a 32-row strip (R13 internals).
// width-35 = 5 taps (stride 7) over width-7 brick maxes; ring tb[5][7].
// CLAMP=false for the 14/16 interior strips.
// ---------------------------------------------------------------------------
template <bool CLAMP>
__device__ __forceinline__ float vcol_scan(const unsigned* __restrict__ base,
                                           int rbase, int col) {
    unsigned s[13];
    unsigned tb[5][7];
    float acc = 0.0f;

    #pragma unroll
    for (int i = 0; i < 13; i++) {
        const int row = CLAMP ? min(max(rbase + i, 0), H - 1) : (rbase + i);
        s[i] = base[row * 256 + col];
    }

    #pragma unroll
    for (int c = 0; c < 9; c++) {
        const unsigned pre5 = hmax2u(s[5], s[6]);
        const unsigned pre4 = hmax2u(s[4], pre5);
        const unsigned pre3 = hmax2u(s[3], pre4);
        const unsigned pre2 = hmax2u(s[2], pre3);
        const unsigned pre1 = hmax2u(s[1], pre2);
        const unsigned pre0 = hmax2u(s[0], pre1);
        const unsigned suf7  = hmax2u(s[6], s[7]);
        const unsigned suf8  = hmax2u(suf7, s[8]);
        const unsigned suf9  = hmax2u(suf8, s[9]);
        const unsigned suf10 = hmax2u(suf9, s[10]);
        const unsigned suf11 = hmax2u(suf10, s[11]);
        const unsigned suf12 = hmax2u(suf11, s[12]);
        unsigned* t = tb[c % 5];
        t[0] = pre0;
        t[1] = hmax2u(pre1, suf7);
        t[2] = hmax2u(pre2, suf8);
        t[3] = hmax2u(pre3, suf9);
        t[4] = hmax2u(pre4, suf10);
        t[5] = hmax2u(pre5, suf11);
        t[6] = suf12;

        if (c < 8) {
            #pragma unroll
            for (int i = 0; i < 6; i++) s[i] = s[i + 7];
            #pragma unroll
            for (int i = 6; i < 13; i++) {
                const int rr = rbase + 7 * (c + 1) + i;
                const int row = CLAMP ? min(max(rr, 0), H - 1) : rr;
                s[i] = base[row * 256 + col];
            }
        }

        if (c >= 4) {
            #pragma unroll
            for (int m = 0; m < 7; m++) {
                if (c < 8 || m < 4) {
                    unsigned v = tb[(c - 4) % 5][m];
                    v = hmax2u(v, tb[(c - 3) % 5][m]);
                    v = hmax2u(v, tb[(c - 2) % 5][m]);
                    v = hmax2u(v, tb[(c - 1) % 5][m]);
                    v = hmax2u(v, tb[c % 5][m]);
                    const float2 f = __half22float2(*reinterpret_cast<__half2*>(&v));
                    acc += f.x + f.y;           // dc >= 0, |.| is identity
                }
            }
        }
    }
    return acc;
}

// ---------------------------------------------------------------------------
// Kernel 2 (R13 internals): vertical 35-tall max + mean. 1024 blocks x 128.
// ---------------------------------------------------------------------------
__global__ __launch_bounds__(128) void vpass_kernel(float* __restrict__ out) {
    const int bx = blockIdx.x;
    const int n  = bx >> 5;
    const int st = (bx >> 1) & 15;
    const int cf = (bx & 1) << 7;
    const int tid = threadIdx.x;
    const int col = cf + tid;

    const unsigned* base = (const unsigned*)(g_hmax + (size_t)n * HW);
    const int rbase = (st << 5) - 17;

    const bool edge = (st == 0) || (st == 15);
    const float acc = edge ? vcol_scan<true>(base, rbase, col)
                           : vcol_scan<false>(base, rbase, col);

    __shared__ float red[4];
    const int lane = tid & 31;
    float a = acc;
    #pragma unroll
    for (int off = 16; off; off >>= 1)
        a += __shfl_down_sync(0xffffffffu, a, off);
    if (lane == 0) red[tid >> 5] = a;
    __syncthreads();
    if (tid < 4) {
        float v = red[tid];
        #pragma unroll
        for (int off = 2; off; off >>= 1)
            v += __shfl_down_sync(0xfu, v, off);
        if (tid == 0) g_partial[bx] = v;
    }

    __shared__ bool is_last;
    if (tid == 0) {
        __threadfence();
        is_last = (atomicAdd(&g_count, 1) == VBLK - 1);
    }
    __syncthreads();
    if (is_last) {
        __threadfence();
        float v = 0.0f;
        #pragma unroll
        for (int k = 0; k < 8; k++)
            v += g_partial[tid + 128 * k];
        #pragma unroll
        for (int off = 16; off; off >>= 1)
            v += __shfl_down_sync(0xffffffffu, v, off);
        if (lane == 0) red[tid >> 5] = v;
        __syncthreads();
        if (tid < 4) {
            float x = red[tid];
            #pragma unroll
            for (int off = 2; off; off >>= 1)
                x += __shfl_down_sync(0xfu, x, off);
            if (tid == 0) {
                out[0] = x * (1.0f / ((float)NIMG * (float)HW));
                g_count = 0;   // reset for graph replay
            }
        }
    }
}

// ---------------------------------------------------------------------------
extern "C" void kernel_launch(void* const* d_in, const int* in_sizes, int n_in,
                              void* d_out, int out_size) {
    const float* img = (const float*)d_in[0];
    float* out = (float*)d_out;

    hpass_kernel<<<NIMG * H / 8, 256>>>(img);
    vpass_kernel<<<VBLK, 128>>>(out);
}

// round 15
// speedup vs baseline: 1.0789x; 1.0789x over previous
#include <cuda_runtime.h>
#include <cuda_fp16.h>
#include <float.h>

#define NIMG 32
#define H    512
#define W    512
#define HW   (H * W)
#define CHW  (3 * HW)

#define NEG2 0xFC00FC00u      // half2(-inf, -inf)

#define VBLK  (NIMG * 16 * 2)        // 1024 blocks: (img, 32-row strip, col half)

__device__ __half g_hmax[NIMG * HW]; // fp16 intermediate (16.75 MB, L2-resident)
__device__ float  g_partial[VBLK];
__device__ int    g_count;           // zero-init; reset by last block

__device__ __forceinline__ unsigned hmax2u(unsigned a, unsigned b) {
    __half2 ha = *reinterpret_cast<__half2*>(&a);
    __half2 hb = *reinterpret_cast<__half2*>(&b);
    __half2 hm = __hmax2(ha, hb);
    return *reinterpret_cast<unsigned*>(&hm);
}
__device__ __forceinline__ unsigned sh1(unsigned a, unsigned b) {
    return __byte_perm(a, b, 0x5432);   // (a.hi, b.lo)
}

// ---------------------------------------------------------------------------
// Kernel 1 — EXACT R13 version (measured best; ~17us wallclock, at LTS cap):
// c = 1 - min3(channels) -> fp16, horizontal 35-wide sliding max, packed half2.
// One block per (n,h) row, 128 threads.
// ---------------------------------------------------------------------------
__global__ __launch_bounds__(128) void hpass_kernel(const float* __restrict__ img) {
    const int row = blockIdx.x;
    const int n   = row >> 9;
    const int h   = row & (H - 1);
    const float* p = img + (size_t)n * CHW + (size_t)h * W;

    __shared__ unsigned s2[276];   // px -20 .. 531
    __shared__ unsigned t2[276];

    const int tid = threadIdx.x;

    if (tid < 20) s2[tid < 10 ? tid : 256 + tid] = NEG2;

    const float4 a = ((const float4*)p)[tid];
    const float4 b = ((const float4*)(p + HW))[tid];
    const float4 c = ((const float4*)(p + 2 * HW))[tid];
    float c0 = 1.0f - fminf(a.x, fminf(b.x, c.x));
    float c1 = 1.0f - fminf(a.y, fminf(b.y, c.y));
    float c2 = 1.0f - fminf(a.z, fminf(b.z, c.z));
    float c3 = 1.0f - fminf(a.w, fminf(b.w, c.w));
    __half2 h01 = __floats2half2_rn(c0, c1);
    __half2 h23 = __floats2half2_rn(c2, c3);
    s2[2 * tid + 10] = *reinterpret_cast<unsigned*>(&h01);
    s2[2 * tid + 11] = *reinterpret_cast<unsigned*>(&h23);
    __syncthreads();

    #pragma unroll
    for (int i = tid; i < 273; i += 128) {
        const unsigned A = s2[i], B = s2[i + 1], C = s2[i + 2];
        t2[i] = hmax2u(hmax2u(hmax2u(A, sh1(A, B)), hmax2u(B, sh1(B, C))), C);
    }
    __syncthreads();

    unsigned* orow = (unsigned*)(g_hmax + (size_t)row * W);
    #pragma unroll
    for (int q = tid; q < 256; q += 128) {
        unsigned v;
        v = sh1(t2[q + 1], t2[q + 2]);
        v = hmax2u(v, t2[q + 4]);
        v = hmax2u(v, sh1(t2[q + 6], t2[q + 7]));
        v = hmax2u(v, t2[q + 9]);
        v = hmax2u(v, sh1(t2[q + 11], t2[q + 12]));
        v = hmax2u(v, t2[q + 14]);
        v = hmax2u(v, sh1(t2[q + 16], t2[q + 17]));
        orow[q] = v;
    }
}

// ---------------------------------------------------------------------------
// Per-thread vertical 35-max column scan over a 32-row strip.
// Same 7-wide/5-tap math as R13, but the tb ring lives in SHARED memory
// (per-thread slice tbs[slot][m][tid]; no cross-thread sharing, no syncs,
// conflict-free). Frees ~30 regs -> much higher occupancy.
// CLAMP=false for the 14/16 interior strips.
// ---------------------------------------------------------------------------
template <bool CLAMP>
__device__ __forceinline__ float vcol_scan(const unsigned* __restrict__ base,
                                           int rbase, int col,
                                           unsigned* __restrict__ tbs) {
    // tbs points at this thread's slice; element (slot, m) at tbs[slot*896 + m*128]
    unsigned s[13];
    float acc = 0.0f;

    #pragma unroll
    for (int i = 0; i < 13; i++) {
        const int row = CLAMP ? min(max(rbase + i, 0), H - 1) : (rbase + i);
        s[i] = base[row * 256 + col];
    }

    #pragma unroll
    for (int c = 0; c < 9; c++) {
        const unsigned pre5 = hmax2u(s[5], s[6]);
        const unsigned pre4 = hmax2u(s[4], pre5);
        const unsigned pre3 = hmax2u(s[3], pre4);
        const unsigned pre2 = hmax2u(s[2], pre3);
        const unsigned pre1 = hmax2u(s[1], pre2);
        const unsigned pre0 = hmax2u(s[0], pre1);
        const unsigned suf7  = hmax2u(s[6], s[7]);
        const unsigned suf8  = hmax2u(suf7, s[8]);
        const unsigned suf9  = hmax2u(suf8, s[9]);
        const unsigned suf10 = hmax2u(suf9, s[10]);
        const unsigned suf11 = hmax2u(suf10, s[11]);
        const unsigned suf12 = hmax2u(suf11, s[12]);
        unsigned* t = tbs + (c % 5) * 896;
        t[0 * 128] = pre0;
        t[1 * 128] = hmax2u(pre1, suf7);
        t[2 * 128] = hmax2u(pre2, suf8);
        t[3 * 128] = hmax2u(pre3, suf9);
        t[4 * 128] = hmax2u(pre4, suf10);
        t[5 * 128] = hmax2u(pre5, suf11);
        t[6 * 128] = suf12;

        if (c < 8) {
            #pragma unroll
            for (int i = 0; i < 6; i++) s[i] = s[i + 7];
            #pragma unroll
            for (int i = 6; i < 13; i++) {
                const int rr = rbase + 7 * (c + 1) + i;
                const int row = CLAMP ? min(max(rr, 0), H - 1) : rr;
                s[i] = base[row * 256 + col];
            }
        }

        if (c >= 4) {
            #pragma unroll
            for (int m = 0; m < 7; m++) {
                if (c < 8 || m < 4) {
                    unsigned v =          tbs[((c - 4) % 5) * 896 + m * 128];
                    v = hmax2u(v, tbs[((c - 3) % 5) * 896 + m * 128]);
                    v = hmax2u(v, tbs[((c - 2) % 5) * 896 + m * 128]);
                    v = hmax2u(v, tbs[((c - 1) % 5) * 896 + m * 128]);
                    v = hmax2u(v, tbs[((c    ) % 5) * 896 + m * 128]);
                    const float2 f = __half22float2(*reinterpret_cast<__half2*>(&v));
                    acc += f.x + f.y;           // dc >= 0, |.| is identity
                }
            }
        }
    }
    return acc;
}

// ---------------------------------------------------------------------------
// Kernel 2: vertical 35-tall max + mean. 1024 blocks x 128 threads.
// smem: tb ring 5*7*128 words (17.5 KB) + reduction scratch.
// ---------------------------------------------------------------------------
__global__ __launch_bounds__(128) void vpass_kernel(float* __restrict__ out) {
    __shared__ unsigned tb_ring[5 * 7 * 128];

    const int bx = blockIdx.x;
    const int n  = bx >> 5;
    const int st = (bx >> 1) & 15;
    const int cf = (bx & 1) << 7;
    const int tid = threadIdx.x;
    const int col = cf + tid;

    const unsigned* base = (const unsigned*)(g_hmax + (size_t)n * HW);
    const int rbase = (st << 5) - 17;
    unsigned* tbs = tb_ring + tid;

    const bool edge = (st == 0) || (st == 15);
    const float acc = edge ? vcol_scan<true>(base, rbase, col, tbs)
                           : vcol_scan<false>(base, rbase, col, tbs);

    // block reduction 128 -> 1
    __shared__ float red[4];
    const int lane = tid & 31;
    float a = acc;
    #pragma unroll
    for (int off = 16; off; off >>= 1)
        a += __shfl_down_sync(0xffffffffu, a, off);
    if (lane == 0) red[tid >> 5] = a;
    __syncthreads();
    if (tid < 4) {
        float v = red[tid];
        #pragma unroll
        for (int off = 2; off; off >>= 1)
            v += __shfl_down_sync(0xfu, v, off);
        if (tid == 0) g_partial[bx] = v;
    }

    // last block: deterministic final reduce + write
    __shared__ bool is_last;
    if (tid == 0) {
        __threadfence();
        is_last = (atomicAdd(&g_count, 1) == VBLK - 1);
    }
    __syncthreads();
    if (is_last) {
        __threadfence();
        float v = 0.0f;
        #pragma unroll
        for (int k = 0; k < 8; k++)
            v += g_partial[tid + 128 * k];
        #pragma unroll
        for (int off = 16; off; off >>= 1)
            v += __shfl_down_sync(0xffffffffu, v, off);
        if (lane == 0) red[tid >> 5] = v;
        __syncthreads();
        if (tid < 4) {
            float x = red[tid];
            #pragma unroll
            for (int off = 2; off; off >>= 1)
                x += __shfl_down_sync(0xfu, x, off);
            if (tid == 0) {
                out[0] = x * (1.0f / ((float)NIMG * (float)HW));
                g_count = 0;   // reset for graph replay
            }
        }
    }
}

// ---------------------------------------------------------------------------
extern "C" void kernel_launch(void* const* d_in, const int* in_sizes, int n_in,
                              void* d_out, int out_size) {
    const float* img = (const float*)d_in[0];
    float* out = (float*)d_out;

    hpass_kernel<<<NIMG * H, 128>>>(img);
    vpass_kernel<<<VBLK, 128>>>(out);
}